// round 11
// baseline (speedup 1.0000x reference)
#include <cuda_runtime.h>
#include <cstdint>

#define B_DIM 64
#define S_DIM 512
#define W_DIM 256
#define D_DIM 768
#define N_DIM 96
#define MT 128
#define KT 64
#define NUM_KT 12
#define THREADS 256

#define ROW_STRIDE 144              // bytes per fp16 tile row (64*2 + 16 pad)
#define SM_A      1024              // after idx area
#define A_STAGE   18432             // 128 * 144
#define SM_B      (SM_A + 2 * A_STAGE)       // 37888
#define B_STAGE   13824             // 96 * 144
#define SMEM_TOTAL (SM_B + 3 * B_STAGE)      // 79360

// Pre-converted fp16 copy of clsw: [96][768] fp16, row stride 1536 B
__device__ __align__(16) unsigned char g_Bh[N_DIM * D_DIM * 2];

static __device__ __forceinline__ uint32_t smem_u32(const void* p) {
    uint32_t a;
    asm("{ .reg .u64 t; cvta.to.shared.u64 t, %1; cvt.u32.u64 %0, t; }" : "=r"(a) : "l"(p));
    return a;
}

static __device__ __forceinline__ void ldsm4(uint32_t* r, uint32_t addr) {
    asm volatile("ldmatrix.sync.aligned.m8n8.x4.shared.b16 {%0,%1,%2,%3}, [%4];"
                 : "=r"(r[0]), "=r"(r[1]), "=r"(r[2]), "=r"(r[3]) : "r"(addr));
}

static __device__ __forceinline__ void mma_f16(float* c, const uint32_t* a, const uint32_t* b) {
    asm volatile(
        "mma.sync.aligned.m16n8k16.row.col.f32.f16.f16.f32 "
        "{%0,%1,%2,%3}, {%4,%5,%6,%7}, {%8,%9}, {%0,%1,%2,%3};"
        : "+f"(c[0]), "+f"(c[1]), "+f"(c[2]), "+f"(c[3])
        : "r"(a[0]), "r"(a[1]), "r"(a[2]), "r"(a[3]), "r"(b[0]), "r"(b[1]));
}

static __device__ __forceinline__ uint2 cvt_f16x4(float4 v) {
    uint2 r;   // low half of each word = lower-k element
    asm("cvt.rn.f16x2.f32 %0, %1, %2;" : "=r"(r.x) : "f"(v.y), "f"(v.x));
    asm("cvt.rn.f16x2.f32 %0, %1, %2;" : "=r"(r.y) : "f"(v.w), "f"(v.z));
    return r;
}

static __device__ __forceinline__ void cp16(uint32_t dst, const void* src) {
    asm volatile("cp.async.cg.shared.global [%0], [%1], 16;" :: "r"(dst), "l"(src) : "memory");
}

static __device__ __forceinline__ void pfL2(const void* p) {
    asm volatile("prefetch.global.L2 [%0];" :: "l"(p));
}

// ---------- kernel 1: convert clsw fp32 -> fp16 scratch ----------
__global__ void cvtB_kernel(const float* __restrict__ clsw) {
    int i = blockIdx.x * blockDim.x + threadIdx.x;   // 18432 float4 chunks
    float4 v = ((const float4*)clsw)[i];
    ((uint2*)g_Bh)[i] = cvt_f16x4(v);
}

// ---------- kernel 2: gathered GEMM + bulk L2 prefetch ----------
__global__ __launch_bounds__(THREADS, 1)
void ner_hmma_kernel(const float* __restrict__ seq, const int* __restrict__ widx,
                     const float* __restrict__ clsb, float* __restrict__ out) {
    extern __shared__ char smem[];
    const uint32_t sb = smem_u32(smem);
    const int tid  = threadIdx.x;
    const int wid  = tid >> 5;
    const int lane = tid & 31;
    const int b  = blockIdx.x >> 1;
    const int w0 = (blockIdx.x & 1) * MT;

    int* idx_s = (int*)smem;
    if (tid < MT) idx_s[tid] = widx[b * W_DIM + w0 + tid];
    __syncthreads();

    // ---- bulk L2 prefetch: the CTA's whole gathered A slab (128 rows x 3 KB)
    // 3072 x 128 B lines, 12 per thread. Fire-and-forget: floods the memory
    // system at max MLP so the pipeline below hits L2, not DRAM.
    {
        const char* base = (const char*)(seq + (size_t)b * S_DIM * D_DIM);
#pragma unroll
        for (int j = 0; j < 12; j++) {
            int u = tid + 256 * j;          // 0..3071
            int row = u / 24, c = u - row * 24;
            pfL2(base + (size_t)idx_s[row] * (D_DIM * 4) + c * 128);
        }
    }

    // ---- producer A mapping: row-slot pr (0..15), float4 k-chunk pk ----
    const int pr = tid >> 4;
    const int pk = (tid & 15) << 2;

    const float* aP[8];
#pragma unroll
    for (int i = 0; i < 8; i++)
        aP[i] = seq + ((size_t)b * S_DIM + idx_s[pr + 16 * i]) * D_DIM + pk;

    uint32_t soA[8];
#pragma unroll
    for (int i = 0; i < 8; i++) soA[i] = (uint32_t)(pr + 16 * i) * ROW_STRIDE + (uint32_t)pk * 2;

    // ---- producer B mapping (cp.async): 3 tasks of 16B each ----
    uint32_t bDst[3];
    const unsigned char* bSrc[3];
#pragma unroll
    for (int j = 0; j < 3; j++) {
        int u = tid + 256 * j;
        int row = u >> 3, c = u & 7;
        bDst[j] = (uint32_t)row * ROW_STRIDE + (uint32_t)c * 16;
        bSrc[j] = g_Bh + (size_t)row * (D_DIM * 2) + c * 16;
    }

    // ---- consumer mapping: 4(M) x 2(N), warp tile 32x48 ----
    const int wm = (wid & 3) * 32;
    const int wn = (wid >> 2) * 48;

    const uint32_t aOff = (uint32_t)(wm + (lane & 15)) * ROW_STRIDE + ((lane >> 4) << 4);
    const uint32_t bOff = (uint32_t)(wn + ((lane >> 4) << 3) + (lane & 7)) * ROW_STRIDE
                        + (((lane >> 3) & 1) << 4);

    float acc[12][4];
#pragma unroll
    for (int i = 0; i < 12; i++)
#pragma unroll
        for (int v = 0; v < 4; v++) acc[i][v] = 0.f;

    // ---- prologue: tile 0 ----
    float4 ra[8];
#pragma unroll
    for (int i = 0; i < 8; i++) ra[i] = *(const float4*)(aP[i]);
#pragma unroll
    for (int j = 0; j < 3; j++) cp16(sb + SM_B + bDst[j], bSrc[j]);
    asm volatile("cp.async.commit_group;" ::: "memory");

    for (int t = 0; t < NUM_KT; t++) {
        const int p = t & 1;
        const int q = t % 3;
        char* bufA = smem + SM_A + p * A_STAGE;

        // convert + store A(t)
#pragma unroll
        for (int i = 0; i < 8; i++) *(uint2*)(bufA + soA[i]) = cvt_f16x4(ra[i]);

        if (t + 1 < NUM_KT) {
            const int kg = (t + 1) * KT;
#pragma unroll
            for (int i = 0; i < 8; i++) ra[i] = *(const float4*)(aP[i] + kg);
            const uint32_t bq = sb + SM_B + ((t + 1) % 3) * B_STAGE;
            const int kb = (t + 1) * (KT * 2);   // byte offset in g_Bh row
#pragma unroll
            for (int j = 0; j < 3; j++) cp16(bq + bDst[j], bSrc[j] + kb);
            asm volatile("cp.async.commit_group;" ::: "memory");
            asm volatile("cp.async.wait_group 1;" ::: "memory");
        } else {
            asm volatile("cp.async.wait_group 0;" ::: "memory");
        }
        __syncthreads();   // publishes A(t) stores + B(t) cp.async to all warps

        const uint32_t sA = sb + SM_A + p * A_STAGE;
        const uint32_t sB = sb + SM_B + q * B_STAGE;
#pragma unroll
        for (int ks = 0; ks < 4; ks++) {
            const uint32_t k0b = (uint32_t)ks * 32;
            uint32_t af[2][4];
#pragma unroll
            for (int i = 0; i < 2; i++)
                ldsm4(af[i], sA + aOff + i * (16 * ROW_STRIDE) + k0b);
            uint32_t bf[3][4];
#pragma unroll
            for (int j = 0; j < 3; j++)
                ldsm4(bf[j], sB + bOff + j * (16 * ROW_STRIDE) + k0b);
#pragma unroll
            for (int i = 0; i < 2; i++)
#pragma unroll
                for (int j2 = 0; j2 < 6; j2++)
                    mma_f16(acc[i * 6 + j2], af[i], &bf[j2 >> 1][(j2 & 1) * 2]);
        }
    }

    // ---- epilogue: scatter to out[a, b, w, c] ----
#pragma unroll
    for (int i = 0; i < 2; i++) {
#pragma unroll
        for (int j2 = 0; j2 < 6; j2++) {
            const float* c = acc[i * 6 + j2];
            const int n_base = wn + j2 * 8 + 2 * (lane & 3);
            const int m_base = wm + i * 16 + (lane >> 2);
#pragma unroll
            for (int v = 0; v < 4; v++) {
                const int n = n_base + (v & 1);
                const int m = m_base + (v >> 1) * 8;
                const int w = w0 + m;
                const int a_ = n / 3;
                const int c_ = n - a_ * 3;
                out[(size_t)a_ * (B_DIM * W_DIM * 3) + (size_t)b * (W_DIM * 3) + w * 3 + c_]
                    = c[v] + clsb[n];
            }
        }
    }
}

extern "C" void kernel_launch(void* const* d_in, const int* in_sizes, int n_in,
                              void* d_out, int out_size) {
    const float* seq  = (const float*)d_in[0];  // [B, S, D] fp32
    const int*   widx = (const int*)d_in[1];    // [B, W] int32
    const float* clsw = (const float*)d_in[2];  // [A*3, D] fp32
    const float* clsb = (const float*)d_in[3];  // [A*3] fp32
    float* out = (float*)d_out;                 // [A, B, W, 3] fp32

    cvtB_kernel<<<36, 512>>>(clsw);
    cudaFuncSetAttribute(ner_hmma_kernel, cudaFuncAttributeMaxDynamicSharedMemorySize, SMEM_TOTAL);
    ner_hmma_kernel<<<128, THREADS, SMEM_TOTAL>>>(seq, widx, clsb, out);
}

// round 12
// speedup vs baseline: 1.0952x; 1.0952x over previous
#include <cuda_runtime.h>
#include <cstdint>

#define B_DIM 64
#define S_DIM 512
#define W_DIM 256
#define D_DIM 768
#define N_DIM 96
#define MT 128
#define KT 64
#define NUM_KT 12
#define THREADS 512

#define A_RS 144                     // A fp16 stage row stride
#define B_RS 1552                    // B fp16 resident row stride (768*2 + 16)
#define A_STAGE 18432                // 128 * 144
#define SM_MBAR 512                  // full[s]=512+16s, empty[s]=512+16s+8
#define SM_A16 1024
#define SM_BB (SM_A16 + 4 * A_STAGE)         // 74752
#define SMEM_TOTAL (SM_BB + N_DIM * B_RS)    // 223744

// Pre-converted fp16 copy of clsw: [96][768] fp16 (linear, 1536 B rows)
__device__ __align__(16) unsigned char g_Bh[N_DIM * D_DIM * 2];

static __device__ __forceinline__ uint32_t smem_u32(const void* p) {
    uint32_t a;
    asm("{ .reg .u64 t; cvta.to.shared.u64 t, %1; cvt.u32.u64 %0, t; }" : "=r"(a) : "l"(p));
    return a;
}

static __device__ __forceinline__ void ldsm4(uint32_t* r, uint32_t addr) {
    asm volatile("ldmatrix.sync.aligned.m8n8.x4.shared.b16 {%0,%1,%2,%3}, [%4];"
                 : "=r"(r[0]), "=r"(r[1]), "=r"(r[2]), "=r"(r[3]) : "r"(addr));
}

static __device__ __forceinline__ void mma_f16(float* c, const uint32_t* a, const uint32_t* b) {
    asm volatile(
        "mma.sync.aligned.m16n8k16.row.col.f32.f16.f16.f32 "
        "{%0,%1,%2,%3}, {%4,%5,%6,%7}, {%8,%9}, {%0,%1,%2,%3};"
        : "+f"(c[0]), "+f"(c[1]), "+f"(c[2]), "+f"(c[3])
        : "r"(a[0]), "r"(a[1]), "r"(a[2]), "r"(a[3]), "r"(b[0]), "r"(b[1]));
}

static __device__ __forceinline__ uint2 cvt_f16x4(float4 v) {
    uint2 r;   // low half of each word = lower-k element
    asm("cvt.rn.f16x2.f32 %0, %1, %2;" : "=r"(r.x) : "f"(v.y), "f"(v.x));
    asm("cvt.rn.f16x2.f32 %0, %1, %2;" : "=r"(r.y) : "f"(v.w), "f"(v.z));
    return r;
}

static __device__ __forceinline__ void cp16(uint32_t dst, const void* src) {
    asm volatile("cp.async.cg.shared.global [%0], [%1], 16;" :: "r"(dst), "l"(src) : "memory");
}

static __device__ __forceinline__ void mbar_init(uint32_t a, uint32_t cnt) {
    asm volatile("mbarrier.init.shared.b64 [%0], %1;" :: "r"(a), "r"(cnt) : "memory");
}

static __device__ __forceinline__ void mbar_arrive(uint32_t a) {
    uint64_t d;
    asm volatile("mbarrier.arrive.shared::cta.b64 %0, [%1];" : "=l"(d) : "r"(a) : "memory");
}

static __device__ __forceinline__ void mbar_wait(uint32_t mbar, uint32_t parity) {
    uint32_t done;
    asm volatile(
        "{\n\t"
        ".reg .pred p;\n\t"
        "mbarrier.try_wait.parity.acquire.cta.shared::cta.b64 p, [%1], %2;\n\t"
        "selp.b32 %0, 1, 0, p;\n\t"
        "}"
        : "=r"(done) : "r"(mbar), "r"(parity) : "memory");
    if (!done) {
        asm volatile(
            "{\n\t"
            ".reg .pred P1;\n\t"
            "LW_%=:\n\t"
            "mbarrier.try_wait.parity.acquire.cta.shared::cta.b64 P1, [%0], %1, 0x989680;\n\t"
            "@P1 bra.uni LD_%=;\n\t"
            "bra.uni LW_%=;\n\t"
            "LD_%=:\n\t"
            "}"
            :: "r"(mbar), "r"(parity) : "memory");
    }
}

// ---------- kernel 1: convert clsw fp32 -> fp16 scratch ----------
__global__ void cvtB_kernel(const float* __restrict__ clsw) {
    int i = blockIdx.x * blockDim.x + threadIdx.x;   // 18432 float4 chunks
    float4 v = ((const float4*)clsw)[i];
    ((uint2*)g_Bh)[i] = cvt_f16x4(v);
}

// ---------- kernel 2: warp-specialized gathered GEMM ----------
__global__ __launch_bounds__(THREADS, 1)
void ner_hmma_kernel(const float* __restrict__ seq, const int* __restrict__ widx,
                     const float* __restrict__ clsb, float* __restrict__ out) {
    extern __shared__ char smem[];
    const uint32_t sb = smem_u32(smem);
    const int tid  = threadIdx.x;
    const int wid  = tid >> 5;
    const int lane = tid & 31;
    const int b  = blockIdx.x >> 1;
    const int w0 = (blockIdx.x & 1) * MT;

    int* idx_s = (int*)smem;
    if (tid < MT) idx_s[tid] = widx[b * W_DIM + w0 + tid];
    if (tid == 0) {
#pragma unroll
        for (int s = 0; s < 4; s++) {
            mbar_init(sb + SM_MBAR + 16 * s, 256);      // full[s]: 256 producer arrivals
            mbar_init(sb + SM_MBAR + 16 * s + 8, 256);  // empty[s]: 256 consumer arrivals
        }
    }
    __syncthreads();

    if (tid < 256) {
        // ================= CONSUMERS (warps 0-7) =================
        // load ALL of B fp16 into resident smem: 9216 x 16B chunks, 36/thread
#pragma unroll
        for (int j = 0; j < 36; j++) {
            int u = tid + 256 * j;
            int row = u / 96, ch = u - row * 96;
            cp16(sb + SM_BB + (uint32_t)row * B_RS + (uint32_t)ch * 16,
                 g_Bh + (size_t)u * 16);
        }
        asm volatile("cp.async.commit_group;" ::: "memory");
        asm volatile("cp.async.wait_group 0;" ::: "memory");
        asm volatile("bar.sync 1, 256;" ::: "memory");   // consumers see full B

        const int wm = (wid & 3) * 32;     // 4(M) x 2(N) warp grid, tile 32x48
        const int wn = (wid >> 2) * 48;
        const uint32_t aOff = (uint32_t)(wm + (lane & 15)) * A_RS + ((lane >> 4) << 4);
        const uint32_t bOff = (uint32_t)(wn + ((lane >> 4) << 3) + (lane & 7)) * B_RS
                            + (((lane >> 3) & 1) << 4);

        float acc[12][4];
#pragma unroll
        for (int i = 0; i < 12; i++)
#pragma unroll
            for (int v = 0; v < 4; v++) acc[i][v] = 0.f;

#pragma unroll
        for (int t = 0; t < NUM_KT; t++) {
            const int s = t & 3;
            const uint32_t phf = (t >> 2) & 1;          // 0,0,0,0,1,1,1,1,0,...
            mbar_wait(sb + SM_MBAR + 16 * s, phf);      // A(t) ready

            const uint32_t sA = sb + SM_A16 + s * A_STAGE;
            const uint32_t bcol = (uint32_t)t * 128;
#pragma unroll
            for (int ks = 0; ks < 4; ks++) {
                const uint32_t k0a = (uint32_t)ks * 32;
                uint32_t af[2][4];
#pragma unroll
                for (int i = 0; i < 2; i++)
                    ldsm4(af[i], sA + aOff + i * (16 * A_RS) + k0a);
                uint32_t bf[3][4];
#pragma unroll
                for (int j = 0; j < 3; j++)
                    ldsm4(bf[j], sb + SM_BB + bOff + j * (16 * B_RS) + bcol + k0a);
#pragma unroll
                for (int i = 0; i < 2; i++)
#pragma unroll
                    for (int j2 = 0; j2 < 6; j2++)
                        mma_f16(acc[i * 6 + j2], af[i], &bf[j2 >> 1][(j2 & 1) * 2]);
            }
            mbar_arrive(sb + SM_MBAR + 16 * s + 8);     // stage s free
        }

        // ---- epilogue ----
#pragma unroll
        for (int i = 0; i < 2; i++) {
#pragma unroll
            for (int j2 = 0; j2 < 6; j2++) {
                const float* c = acc[i * 6 + j2];
                const int n_base = wn + j2 * 8 + 2 * (lane & 3);
                const int m_base = wm + i * 16 + (lane >> 2);
#pragma unroll
                for (int v = 0; v < 4; v++) {
                    const int n = n_base + (v & 1);
                    const int m = m_base + (v >> 1) * 8;
                    const int w = w0 + m;
                    const int a_ = n / 3;
                    const int c_ = n - a_ * 3;
                    out[(size_t)a_ * (B_DIM * W_DIM * 3) + (size_t)b * (W_DIM * 3) + w * 3 + c_]
                        = c[v] + clsb[n];
                }
            }
        }
    } else {
        // ================= PRODUCERS (warps 8-15) =================
        const int tp = tid - 256;                  // 0..255
        // 2048 chunks of 16B per tile, 8/thread: row = (tp>>4)+16j, ch = tp&15
        const float* aSrc[8];
        uint32_t aDst[8];
#pragma unroll
        for (int j = 0; j < 8; j++) {
            int row = (tp >> 4) + 16 * j;
            int ch  = tp & 15;
            aSrc[j] = seq + ((size_t)b * S_DIM + idx_s[row]) * D_DIM + ch * 4;
            aDst[j] = (uint32_t)row * A_RS + (uint32_t)ch * 8;
        }

        float4 ra[2][8];
#pragma unroll
        for (int j = 0; j < 8; j++) ra[0][j] = *(const float4*)(aSrc[j]);

#pragma unroll
        for (int t = 0; t < NUM_KT; t++) {
            const int s  = t & 3;
            const int cb = t & 1;
            // prefetch A(t+1) while (possibly) waiting for the stage
            if (t + 1 < NUM_KT) {
                const int kg = (t + 1) * KT;
#pragma unroll
                for (int j = 0; j < 8; j++) ra[cb ^ 1][j] = *(const float4*)(aSrc[j] + kg);
            }
            const uint32_t phe = 1u ^ ((t >> 2) & 1);   // 1,1,1,1,0,0,0,0,1,...
            mbar_wait(sb + SM_MBAR + 16 * s + 8, phe);  // stage s free

            char* st = smem + SM_A16 + s * A_STAGE;
#pragma unroll
            for (int j = 0; j < 8; j++) *(uint2*)(st + aDst[j]) = cvt_f16x4(ra[cb][j]);
            mbar_arrive(sb + SM_MBAR + 16 * s);         // A(t) published (release)
        }
    }
}

extern "C" void kernel_launch(void* const* d_in, const int* in_sizes, int n_in,
                              void* d_out, int out_size) {
    const float* seq  = (const float*)d_in[0];  // [B, S, D] fp32
    const int*   widx = (const int*)d_in[1];    // [B, W] int32
    const float* clsw = (const float*)d_in[2];  // [A*3, D] fp32
    const float* clsb = (const float*)d_in[3];  // [A*3] fp32
    float* out = (float*)d_out;                 // [A, B, W, 3] fp32

    cvtB_kernel<<<36, 512>>>(clsw);
    cudaFuncSetAttribute(ner_hmma_kernel, cudaFuncAttributeMaxDynamicSharedMemorySize, SMEM_TOTAL);
    ner_hmma_kernel<<<128, THREADS, SMEM_TOTAL>>>(seq, widx, clsb, out);
}